// round 9
// baseline (speedup 1.0000x reference)
#include <cuda_runtime.h>

#define MAXPTS 50000
#define NBLK 592
#define CONVBLK 444

// ---------------- scratch (no allocation allowed) ----------------
__device__ __align__(16) float  g_y1[MAXPTS * 32];    // unary1 pre-BN
__device__ __align__(16) float  g_y2[MAXPTS * 32];    // conv output pre-BN
__device__ __align__(16) float  g_z[MAXPTS * 128];    // unary2 pre-BN
__device__ double g_acc[384];  // [0:32) sum1 [32:64) sq1 [64:96) sumC [96:128) sqC [128:256) sum3 [256:384) sq3

__device__ __forceinline__ float lrelu(float x) { return fmaxf(x, 0.1f * x); }

// compute BN affine from accumulated stats: a = g/sqrt(var+eps), c = b - mean*a
__device__ __forceinline__ void bn_affine(const double* __restrict__ sum,
                                          const double* __restrict__ sq,
                                          const float* __restrict__ g,
                                          const float* __restrict__ b,
                                          double invM, int t,
                                          float* __restrict__ a, float* __restrict__ c) {
    double mean = sum[t] * invM;
    double var  = sq[t] * invM - mean * mean;
    float inv = (float)(1.0 / sqrt(var + 1e-5));
    float av = g[t] * inv;
    a[t] = av;
    c[t] = b[t] - (float)mean * av;
}

// ---------------- K1: y1 = s_feats @ w_u1  (M,128)x(128,32), + column stats ----------------
// block 0 also resets stage-2 acc slots (consumed by kpi_final in the previous replay)
__global__ void __launch_bounds__(256) kpi_u1_kernel(const float* __restrict__ sf,
                                                     const float* __restrict__ w, int M) {
    __shared__ __align__(16) float w_s[4096];        // [c2][c] 128x32
    __shared__ __align__(16) float rows_s[32][128];
    __shared__ float red_s[8][32];
    int tid = threadIdx.x;
    if (blockIdx.x == 0) {
        if (tid < 256) g_acc[128 + tid] = 0.0;
    }
    for (int i = tid; i < 4096; i += 256) w_s[i] = w[i];
    int c = tid & 31, rq = tid >> 5;
    float fsum = 0.f, fsq = 0.f;
    int ntile = (M + 31) >> 5;
    for (int T = blockIdx.x; T < ntile; T += gridDim.x) {
        int base = T << 5;
        __syncthreads();
        for (int i = tid; i < 1024; i += 256) {
            int r = i >> 5, c4 = i & 31;
            int m = base + r;
            float4 v = make_float4(0.f, 0.f, 0.f, 0.f);
            if (m < M) v = reinterpret_cast<const float4*>(sf)[m * 32 + c4];
            reinterpret_cast<float4*>(&rows_s[r][0])[c4] = v;
        }
        __syncthreads();
        float a0 = 0.f, a1 = 0.f, a2 = 0.f, a3 = 0.f;
#pragma unroll
        for (int c2 = 0; c2 < 128; c2 += 4) {
            float w0 = w_s[c2 * 32 + c], w1 = w_s[(c2 + 1) * 32 + c];
            float w2 = w_s[(c2 + 2) * 32 + c], w3 = w_s[(c2 + 3) * 32 + c];
            float4 r0 = reinterpret_cast<const float4*>(&rows_s[rq][0])[c2 >> 2];
            float4 r1 = reinterpret_cast<const float4*>(&rows_s[rq + 8][0])[c2 >> 2];
            float4 r2 = reinterpret_cast<const float4*>(&rows_s[rq + 16][0])[c2 >> 2];
            float4 r3 = reinterpret_cast<const float4*>(&rows_s[rq + 24][0])[c2 >> 2];
            a0 = fmaf(r0.x, w0, a0); a0 = fmaf(r0.y, w1, a0); a0 = fmaf(r0.z, w2, a0); a0 = fmaf(r0.w, w3, a0);
            a1 = fmaf(r1.x, w0, a1); a1 = fmaf(r1.y, w1, a1); a1 = fmaf(r1.z, w2, a1); a1 = fmaf(r1.w, w3, a1);
            a2 = fmaf(r2.x, w0, a2); a2 = fmaf(r2.y, w1, a2); a2 = fmaf(r2.z, w2, a2); a2 = fmaf(r2.w, w3, a2);
            a3 = fmaf(r3.x, w0, a3); a3 = fmaf(r3.y, w1, a3); a3 = fmaf(r3.z, w2, a3); a3 = fmaf(r3.w, w3, a3);
        }
        int m;
        m = base + rq;      if (m < M) { g_y1[m * 32 + c] = a0; fsum += a0; fsq += a0 * a0; }
        m = base + rq + 8;  if (m < M) { g_y1[m * 32 + c] = a1; fsum += a1; fsq += a1 * a1; }
        m = base + rq + 16; if (m < M) { g_y1[m * 32 + c] = a2; fsum += a2; fsq += a2 * a2; }
        m = base + rq + 24; if (m < M) { g_y1[m * 32 + c] = a3; fsum += a3; fsq += a3 * a3; }
    }
    __syncthreads();
    red_s[rq][c] = fsum; __syncthreads();
    if (rq == 0) {
        float s = 0.f;
#pragma unroll
        for (int i = 0; i < 8; i++) s += red_s[i][c];
        atomicAdd(&g_acc[c], (double)s);
    }
    __syncthreads();
    red_s[rq][c] = fsq; __syncthreads();
    if (rq == 0) {
        float s = 0.f;
#pragma unroll
        for (int i = 0; i < 8; i++) s += red_s[i][c];
        atomicAdd(&g_acc[32 + c], (double)s);
    }
}

// ---------------- K3: KPInv conv (warp per point); computes unary1 BN affine per-block ----------------
__global__ void __launch_bounds__(256, 3) kpi_conv_kernel(const float* __restrict__ qp,
                                                          const float* __restrict__ sp,
                                                          const int* __restrict__ nidx,
                                                          const float* __restrict__ kp,
                                                          const float* __restrict__ wg1,
                                                          const float* __restrict__ bg1,
                                                          const float* __restrict__ wg2,
                                                          const float* __restrict__ bg2,
                                                          const float* __restrict__ gu1,
                                                          const float* __restrict__ bu1,
                                                          double invM, int M) {
    __shared__ __align__(16) float omg_s[8][32][2];
    __shared__ __align__(16) float center_s[8][32];
    __shared__ float hid_s[8][8];
    __shared__ float wv_s[8][32];
    __shared__ __align__(16) float4 kp_s[15];   // x,y,z,|k|^2
    __shared__ float wg1_s[32][8];
    __shared__ float bg1_s[8];
    __shared__ float wg2_s[8][32];    // 30 used per row
    __shared__ float bg2_s[32];
    __shared__ __align__(16) float red_s[8][32];
    __shared__ __align__(16) float s_a1[32];
    __shared__ __align__(16) float s_c1[32];

    const unsigned FULL = 0xffffffffu;
    int tid = threadIdx.x, wid = tid >> 5, t = tid & 31;
    int r = t >> 3, q = t & 7;        // lane = r*8 + q
    // per-block BN affine for unary1 output (stage 0)
    if (tid < 32) bn_affine(g_acc, g_acc + 32, gu1, bu1, invM, tid, s_a1, s_c1);
    // load small params
    if (tid >= 32 && tid < 47) {
        int kk = tid - 32;
        float kx = kp[3 * kk], ky = kp[3 * kk + 1], kz = kp[3 * kk + 2];
        kp_s[kk] = make_float4(kx, ky, kz, kx * kx + ky * ky + kz * kz);
    }
    for (int i = tid; i < 256; i += 256) wg1_s[i >> 3][i & 7] = wg1[i];
    if (tid >= 64 && tid < 72) bg1_s[tid - 64] = bg1[tid - 64];
    if (tid < 240) wg2_s[tid / 30][tid % 30] = wg2[tid];
    if (tid >= 96 && tid < 126) bg2_s[tid - 96] = bg2[tid - 96];
    __syncthreads();

    // per-lane BN affine for channels 4q..4q+3
    float4 a1q = reinterpret_cast<const float4*>(s_a1)[q];
    float4 c1q = reinterpret_cast<const float4*>(s_c1)[q];
    const float4* gy4 = reinterpret_cast<const float4*>(g_y1);

    int stride = gridDim.x * 8;
    int m = blockIdx.x * 8 + wid;
    // initial prefetch (every warp has at least one point: 3552 <= M)
    int j = nidx[m * 32 + t];
    float qx = qp[3 * m], qy = qp[3 * m + 1], qz = qp[3 * m + 2];

    float4 fsum4 = make_float4(0.f, 0.f, 0.f, 0.f);
    float4 fsq4  = make_float4(0.f, 0.f, 0.f, 0.f);

    for (; m < M; m += stride) {
        // positions: lane = neighbor h
        float nx = sp[3 * j] - qx, ny = sp[3 * j + 1] - qy, nz = sp[3 * j + 2] - qz;
        float nn = nx * nx + ny * ny + nz * nz;

        // prefetch next point's indices / query position
        int mn = m + stride;
        int jn = 0; float qxn = 0.f, qyn = 0.f, qzn = 0.f;
        if (mn < M) {
            jn = nidx[mn * 32 + t];
            qxn = qp[3 * mn]; qyn = qp[3 * mn + 1]; qzn = qp[3 * mn + 2];
        }

        // gather: iteration i loads row h = 4*i + r, channels 4q..4q+3 (LDG.128)
        float4 v4[8];
        float4 cmax4 = make_float4(-3.4e38f, -3.4e38f, -3.4e38f, -3.4e38f);
#pragma unroll
        for (int i = 0; i < 8; i++) {
            int jh = __shfl_sync(FULL, j, 4 * i + r);
            float4 raw = gy4[jh * 8 + q];
            float4 vv;
            vv.x = lrelu(fmaf(raw.x, a1q.x, c1q.x));
            vv.y = lrelu(fmaf(raw.y, a1q.y, c1q.y));
            vv.z = lrelu(fmaf(raw.z, a1q.z, c1q.z));
            vv.w = lrelu(fmaf(raw.w, a1q.w, c1q.w));
            v4[i] = vv;
            cmax4.x = fmaxf(cmax4.x, vv.x); cmax4.y = fmaxf(cmax4.y, vv.y);
            cmax4.z = fmaxf(cmax4.z, vv.z); cmax4.w = fmaxf(cmax4.w, vv.w);
        }
        // butterfly max across r (bits 3,4 of lane id)
#pragma unroll
        for (int ofs = 8; ofs <= 16; ofs <<= 1) {
            cmax4.x = fmaxf(cmax4.x, __shfl_xor_sync(FULL, cmax4.x, ofs));
            cmax4.y = fmaxf(cmax4.y, __shfl_xor_sync(FULL, cmax4.y, ofs));
            cmax4.z = fmaxf(cmax4.z, __shfl_xor_sync(FULL, cmax4.z, ofs));
            cmax4.w = fmaxf(cmax4.w, __shfl_xor_sync(FULL, cmax4.w, ofs));
        }
        if (r == 0) reinterpret_cast<float4*>(&center_s[wid][0])[q] = cmax4;
        __syncwarp();

        // hidden[q] = lrelu(b1[q] + sum_c center[c]*wg1[c][q]); split channel range over r
        {
            float a = 0.f;
#pragma unroll
            for (int e = 0; e < 8; e++)
                a = fmaf(center_s[wid][r * 8 + e], wg1_s[r * 8 + e][q], a);
            a += __shfl_xor_sync(FULL, a, 8);
            a += __shfl_xor_sync(FULL, a, 16);
            if (t < 8) hid_s[wid][t] = lrelu(a + bg1_s[t]);
        }
        __syncwarp();
        // w = hidden @ w_g2 + b_g2, lanes 0..29  (w[k,g] = w[2k+g])
        if (t < 30) {
            float a = bg2_s[t];
#pragma unroll
            for (int k8 = 0; k8 < 8; k8++) a = fmaf(hid_s[wid][k8], wg2_s[k8][t], a);
            wv_s[wid][t] = a;
        }
        __syncwarp();
        // omega[h,g] = sum_k w[k,g] * infl[h,k]; lane = neighbor h; infl fused
        float om0 = 0.f, om1 = 0.f;
#pragma unroll
        for (int k = 0; k < 15; k++) {
            float4 kk = kp_s[k];
            float d2 = nn + kk.w - 2.f * (nx * kk.x + ny * kk.y + nz * kk.z);
            float infl = fmaxf(1.f - sqrtf(fmaxf(d2, 0.f)), 0.f);
            om0 = fmaf(wv_s[wid][2 * k], infl, om0);
            om1 = fmaf(wv_s[wid][2 * k + 1], infl, om1);
        }
        omg_s[wid][t][0] = om0;
        omg_s[wid][t][1] = om1;
        __syncwarp();
        // out[4q+e] = sum_h omega[h, g] * v[h][4q+e]; g = q>>2; rows h = 4i+r
        int g = q >> 2;
        float4 o4 = make_float4(0.f, 0.f, 0.f, 0.f);
#pragma unroll
        for (int i = 0; i < 8; i++) {
            float w = omg_s[wid][4 * i + r][g];
            o4.x = fmaf(w, v4[i].x, o4.x);
            o4.y = fmaf(w, v4[i].y, o4.y);
            o4.z = fmaf(w, v4[i].z, o4.z);
            o4.w = fmaf(w, v4[i].w, o4.w);
        }
#pragma unroll
        for (int ofs = 8; ofs <= 16; ofs <<= 1) {
            o4.x += __shfl_xor_sync(FULL, o4.x, ofs);
            o4.y += __shfl_xor_sync(FULL, o4.y, ofs);
            o4.z += __shfl_xor_sync(FULL, o4.z, ofs);
            o4.w += __shfl_xor_sync(FULL, o4.w, ofs);
        }
        if (r == 0) {
            reinterpret_cast<float4*>(g_y2 + m * 32)[q] = o4;
            fsum4.x += o4.x; fsum4.y += o4.y; fsum4.z += o4.z; fsum4.w += o4.w;
            fsq4.x = fmaf(o4.x, o4.x, fsq4.x); fsq4.y = fmaf(o4.y, o4.y, fsq4.y);
            fsq4.z = fmaf(o4.z, o4.z, fsq4.z); fsq4.w = fmaf(o4.w, o4.w, fsq4.w);
        }
        j = jn; qx = qxn; qy = qyn; qz = qzn;
    }
    // block-reduce column stats (channels 4q+e live in lanes r==0)
    __syncthreads();
    if (r == 0) reinterpret_cast<float4*>(&red_s[wid][0])[q] = fsum4;
    __syncthreads();
    if (wid == 0) {
        float s = 0.f;
#pragma unroll
        for (int i = 0; i < 8; i++) s += red_s[i][t];
        atomicAdd(&g_acc[64 + t], (double)s);
    }
    __syncthreads();
    if (r == 0) reinterpret_cast<float4*>(&red_s[wid][0])[q] = fsq4;
    __syncthreads();
    if (wid == 0) {
        float s = 0.f;
#pragma unroll
        for (int i = 0; i < 8; i++) s += red_s[i][t];
        atomicAdd(&g_acc[96 + t], (double)s);
    }
}

// ---------------- K5: z = lrelu(bn(y2)) @ w_u2  (M,32)x(32,128), + column stats ----------------
// computes conv BN affine per-block; block 0 resets stage-0 acc slots
__global__ void __launch_bounds__(256) kpi_u2_kernel(const float* __restrict__ w,
                                                     const float* __restrict__ gc,
                                                     const float* __restrict__ bc,
                                                     double invM, int M) {
    __shared__ __align__(16) float w_s[4096];     // [c2][j] 32x128
    __shared__ __align__(16) float xs[8][32];
    __shared__ float red_s[2][128];
    __shared__ float s_aC[32], s_cC[32];
    int tid = threadIdx.x;
    if (tid < 32) bn_affine(g_acc + 64, g_acc + 96, gc, bc, invM, tid, s_aC, s_cC);
    if (blockIdx.x == 0 && tid >= 64 && tid < 128) g_acc[tid - 64] = 0.0;
    for (int i = tid; i < 4096; i += 256) w_s[i] = w[i];
    int j = tid & 127, rr = tid >> 7;
    float fsum = 0.f, fsq = 0.f;
    int ntile = (M + 7) >> 3;
    for (int T = blockIdx.x; T < ntile; T += gridDim.x) {
        int base = T << 3;
        __syncthreads();
        {
            int r = tid >> 5, cc = tid & 31;
            int m = base + r;
            float v = 0.f;
            if (m < M) {
                v = g_y2[m * 32 + cc];
                v = lrelu(fmaf(v, s_aC[cc], s_cC[cc]));
            }
            xs[r][cc] = v;
        }
        __syncthreads();
        float a0 = 0.f, a1 = 0.f, a2 = 0.f, a3 = 0.f;
#pragma unroll
        for (int c2 = 0; c2 < 32; c2 += 4) {
            float4 x0 = reinterpret_cast<const float4*>(&xs[rr][0])[c2 >> 2];
            float4 x1 = reinterpret_cast<const float4*>(&xs[rr + 2][0])[c2 >> 2];
            float4 x2 = reinterpret_cast<const float4*>(&xs[rr + 4][0])[c2 >> 2];
            float4 x3 = reinterpret_cast<const float4*>(&xs[rr + 6][0])[c2 >> 2];
            float w0 = w_s[c2 * 128 + j], w1 = w_s[(c2 + 1) * 128 + j];
            float w2 = w_s[(c2 + 2) * 128 + j], w3 = w_s[(c2 + 3) * 128 + j];
            a0 = fmaf(x0.x, w0, a0); a0 = fmaf(x0.y, w1, a0); a0 = fmaf(x0.z, w2, a0); a0 = fmaf(x0.w, w3, a0);
            a1 = fmaf(x1.x, w0, a1); a1 = fmaf(x1.y, w1, a1); a1 = fmaf(x1.z, w2, a1); a1 = fmaf(x1.w, w3, a1);
            a2 = fmaf(x2.x, w0, a2); a2 = fmaf(x2.y, w1, a2); a2 = fmaf(x2.z, w2, a2); a2 = fmaf(x2.w, w3, a2);
            a3 = fmaf(x3.x, w0, a3); a3 = fmaf(x3.y, w1, a3); a3 = fmaf(x3.z, w2, a3); a3 = fmaf(x3.w, w3, a3);
        }
        int m;
        m = base + rr;     if (m < M) { g_z[m * 128 + j] = a0; fsum += a0; fsq += a0 * a0; }
        m = base + rr + 2; if (m < M) { g_z[m * 128 + j] = a1; fsum += a1; fsq += a1 * a1; }
        m = base + rr + 4; if (m < M) { g_z[m * 128 + j] = a2; fsum += a2; fsq += a2 * a2; }
        m = base + rr + 6; if (m < M) { g_z[m * 128 + j] = a3; fsum += a3; fsq += a3 * a3; }
    }
    __syncthreads();
    red_s[rr][j] = fsum; __syncthreads();
    if (rr == 0) atomicAdd(&g_acc[128 + j], (double)(red_s[0][j] + red_s[1][j]));
    __syncthreads();
    red_s[rr][j] = fsq; __syncthreads();
    if (rr == 0) atomicAdd(&g_acc[256 + j], (double)(red_s[0][j] + red_s[1][j]));
}

// ---------------- K7: out = lrelu(bn(z) + s_feats) ----------------
// computes unary2 BN affine per-block; block 0 resets stage-1 acc slots
__global__ void __launch_bounds__(256) kpi_final_kernel(const float* __restrict__ sf,
                                                        float* __restrict__ out,
                                                        const float* __restrict__ gu2,
                                                        const float* __restrict__ bu2,
                                                        double invM, int n4) {
    __shared__ __align__(16) float s_a3[128];
    __shared__ __align__(16) float s_c3[128];
    int tid = threadIdx.x;
    if (tid < 128) bn_affine(g_acc + 128, g_acc + 256, gu2, bu2, invM, tid, s_a3, s_c3);
    if (blockIdx.x == 0 && tid >= 128 && tid < 192) g_acc[tid - 64] = 0.0;
    __syncthreads();
    int i = blockIdx.x * blockDim.x + tid;
    int stride = gridDim.x * blockDim.x;
    for (; i < n4; i += stride) {
        float4 z = reinterpret_cast<const float4*>(g_z)[i];
        float4 s = reinterpret_cast<const float4*>(sf)[i];
        int c = (i << 2) & 127;
        float4 r;
        r.x = lrelu(fmaf(z.x, s_a3[c + 0], s_c3[c + 0]) + s.x);
        r.y = lrelu(fmaf(z.y, s_a3[c + 1], s_c3[c + 1]) + s.y);
        r.z = lrelu(fmaf(z.z, s_a3[c + 2], s_c3[c + 2]) + s.z);
        r.w = lrelu(fmaf(z.w, s_a3[c + 3], s_c3[c + 3]) + s.w);
        reinterpret_cast<float4*>(out)[i] = r;
    }
}

// ---------------- launch ----------------
extern "C" void kernel_launch(void* const* d_in, const int* in_sizes, int n_in,
                              void* d_out, int out_size) {
    const float* q_pts   = (const float*)d_in[0];
    const float* s_pts   = (const float*)d_in[1];
    const float* s_feats = (const float*)d_in[2];
    const int*   nidx    = (const int*)d_in[3];
    const float* kp      = (const float*)d_in[4];
    const float* w_u1    = (const float*)d_in[5];
    const float* g_u1    = (const float*)d_in[6];
    const float* b_u1    = (const float*)d_in[7];
    const float* w_g1    = (const float*)d_in[8];
    const float* b_g1    = (const float*)d_in[9];
    const float* w_g2    = (const float*)d_in[10];
    const float* b_g2    = (const float*)d_in[11];
    const float* g_c     = (const float*)d_in[12];
    const float* b_c     = (const float*)d_in[13];
    const float* w_u2    = (const float*)d_in[14];
    const float* g_u2    = (const float*)d_in[15];
    const float* b_u2    = (const float*)d_in[16];
    float* out = (float*)d_out;

    int M = in_sizes[0] / 3;
    double invM = 1.0 / (double)M;

    kpi_u1_kernel<<<NBLK, 256>>>(s_feats, w_u1, M);
    kpi_conv_kernel<<<CONVBLK, 256>>>(q_pts, s_pts, nidx, kp, w_g1, b_g1, w_g2, b_g2,
                                      g_u1, b_u1, invM, M);
    kpi_u2_kernel<<<NBLK, 256>>>(w_u2, g_c, b_c, invM, M);
    kpi_final_kernel<<<1184, 256>>>(s_feats, out, g_u2, b_u2, invM, M * 32);
}

// round 12
// speedup vs baseline: 1.5775x; 1.5775x over previous
#include <cuda_runtime.h>

#define MAXPTS 50000
#define NBLK 592
#define CONVBLK 444

// ---------------- scratch (no allocation allowed) ----------------
__device__ __align__(16) float  g_y1[MAXPTS * 32];    // unary1 pre-BN
__device__ __align__(16) float  g_y2[MAXPTS * 32];    // conv output pre-BN
__device__ __align__(16) float  g_z[MAXPTS * 128];    // unary2 pre-BN
__device__ double g_acc[384];  // [0:32) sum1 [32:64) sq1 [64:96) sumC [96:128) sqC [128:256) sum3 [256:384) sq3

__device__ __forceinline__ float lrelu(float x) { return fmaxf(x, 0.1f * x); }

// compute BN affine from accumulated stats: a = g/sqrt(var+eps), c = b - mean*a
// all-float path (DP only for the two cheap multiplies); rsqrtf + 1 Newton step
__device__ __forceinline__ void bn_affine(const double* __restrict__ sum,
                                          const double* __restrict__ sq,
                                          const float* __restrict__ g,
                                          const float* __restrict__ b,
                                          double invM, int t,
                                          float* __restrict__ a, float* __restrict__ c) {
    float mean = (float)(sum[t] * invM);
    float ex2  = (float)(sq[t]  * invM);
    float x = fmaxf(ex2 - mean * mean, 0.f) + 1e-5f;
    float inv = rsqrtf(x);
    inv = inv * (1.5f - 0.5f * x * inv * inv);   // Newton refine to full fp32
    float av = g[t] * inv;
    a[t] = av;
    c[t] = b[t] - mean * av;
}

// ---------------- K1: y1 = s_feats @ w_u1  (M,128)x(128,32), + column stats ----------------
// block 0 also resets stage-2 acc slots (consumed by kpi_final in the previous replay)
__global__ void __launch_bounds__(256) kpi_u1_kernel(const float* __restrict__ sf,
                                                     const float* __restrict__ w, int M) {
    __shared__ __align__(16) float w_s[4096];        // [c2][c] 128x32
    __shared__ __align__(16) float rows_s[32][128];
    __shared__ float red_s[8][32];
    int tid = threadIdx.x;
    if (blockIdx.x == 0) {
        g_acc[128 + tid] = 0.0;
    }
    for (int i = tid; i < 4096; i += 256) w_s[i] = w[i];
    int c = tid & 31, rq = tid >> 5;
    float fsum = 0.f, fsq = 0.f;
    int ntile = (M + 31) >> 5;
    for (int T = blockIdx.x; T < ntile; T += gridDim.x) {
        int base = T << 5;
        __syncthreads();
        for (int i = tid; i < 1024; i += 256) {
            int r = i >> 5, c4 = i & 31;
            int m = base + r;
            float4 v = make_float4(0.f, 0.f, 0.f, 0.f);
            if (m < M) v = reinterpret_cast<const float4*>(sf)[m * 32 + c4];
            reinterpret_cast<float4*>(&rows_s[r][0])[c4] = v;
        }
        __syncthreads();
        float a0 = 0.f, a1 = 0.f, a2 = 0.f, a3 = 0.f;
#pragma unroll
        for (int c2 = 0; c2 < 128; c2 += 4) {
            float w0 = w_s[c2 * 32 + c], w1 = w_s[(c2 + 1) * 32 + c];
            float w2 = w_s[(c2 + 2) * 32 + c], w3 = w_s[(c2 + 3) * 32 + c];
            float4 r0 = reinterpret_cast<const float4*>(&rows_s[rq][0])[c2 >> 2];
            float4 r1 = reinterpret_cast<const float4*>(&rows_s[rq + 8][0])[c2 >> 2];
            float4 r2 = reinterpret_cast<const float4*>(&rows_s[rq + 16][0])[c2 >> 2];
            float4 r3 = reinterpret_cast<const float4*>(&rows_s[rq + 24][0])[c2 >> 2];
            a0 = fmaf(r0.x, w0, a0); a0 = fmaf(r0.y, w1, a0); a0 = fmaf(r0.z, w2, a0); a0 = fmaf(r0.w, w3, a0);
            a1 = fmaf(r1.x, w0, a1); a1 = fmaf(r1.y, w1, a1); a1 = fmaf(r1.z, w2, a1); a1 = fmaf(r1.w, w3, a1);
            a2 = fmaf(r2.x, w0, a2); a2 = fmaf(r2.y, w1, a2); a2 = fmaf(r2.z, w2, a2); a2 = fmaf(r2.w, w3, a2);
            a3 = fmaf(r3.x, w0, a3); a3 = fmaf(r3.y, w1, a3); a3 = fmaf(r3.z, w2, a3); a3 = fmaf(r3.w, w3, a3);
        }
        int m;
        m = base + rq;      if (m < M) { g_y1[m * 32 + c] = a0; fsum += a0; fsq += a0 * a0; }
        m = base + rq + 8;  if (m < M) { g_y1[m * 32 + c] = a1; fsum += a1; fsq += a1 * a1; }
        m = base + rq + 16; if (m < M) { g_y1[m * 32 + c] = a2; fsum += a2; fsq += a2 * a2; }
        m = base + rq + 24; if (m < M) { g_y1[m * 32 + c] = a3; fsum += a3; fsq += a3 * a3; }
    }
    __syncthreads();
    red_s[rq][c] = fsum; __syncthreads();
    if (rq == 0) {
        float s = 0.f;
#pragma unroll
        for (int i = 0; i < 8; i++) s += red_s[i][c];
        atomicAdd(&g_acc[c], (double)s);
    }
    __syncthreads();
    red_s[rq][c] = fsq; __syncthreads();
    if (rq == 0) {
        float s = 0.f;
#pragma unroll
        for (int i = 0; i < 8; i++) s += red_s[i][c];
        atomicAdd(&g_acc[32 + c], (double)s);
    }
}

// ---------------- K3: KPInv conv (warp per point); computes unary1 BN affine per-block ----------------
__global__ void __launch_bounds__(256, 3) kpi_conv_kernel(const float* __restrict__ qp,
                                                          const float* __restrict__ sp,
                                                          const int* __restrict__ nidx,
                                                          const float* __restrict__ kp,
                                                          const float* __restrict__ wg1,
                                                          const float* __restrict__ bg1,
                                                          const float* __restrict__ wg2,
                                                          const float* __restrict__ bg2,
                                                          const float* __restrict__ gu1,
                                                          const float* __restrict__ bu1,
                                                          double invM, int M) {
    __shared__ __align__(16) float omg_s[8][32][2];
    __shared__ __align__(16) float center_s[8][32];
    __shared__ float hid_s[8][8];
    __shared__ float wv_s[8][32];
    __shared__ __align__(16) float4 kp_s[15];   // x,y,z,|k|^2
    __shared__ float wg1_s[32][8];
    __shared__ float bg1_s[8];
    __shared__ float wg2_s[8][32];    // 30 used per row
    __shared__ float bg2_s[32];
    __shared__ __align__(16) float red_s[8][32];
    __shared__ __align__(16) float s_a1[32];
    __shared__ __align__(16) float s_c1[32];

    const unsigned FULL = 0xffffffffu;
    int tid = threadIdx.x, wid = tid >> 5, t = tid & 31;
    int r = t >> 3, q = t & 7;        // lane = r*8 + q
    // per-block BN affine for unary1 output (stage 0) — float path
    if (tid < 32) bn_affine(g_acc, g_acc + 32, gu1, bu1, invM, tid, s_a1, s_c1);
    // load small params
    if (tid >= 32 && tid < 47) {
        int kk = tid - 32;
        float kx = kp[3 * kk], ky = kp[3 * kk + 1], kz = kp[3 * kk + 2];
        kp_s[kk] = make_float4(kx, ky, kz, kx * kx + ky * ky + kz * kz);
    }
    for (int i = tid; i < 256; i += 256) wg1_s[i >> 3][i & 7] = wg1[i];
    if (tid >= 64 && tid < 72) bg1_s[tid - 64] = bg1[tid - 64];
    if (tid < 240) wg2_s[tid / 30][tid % 30] = wg2[tid];
    if (tid >= 96 && tid < 126) bg2_s[tid - 96] = bg2[tid - 96];
    __syncthreads();

    // per-lane BN affine for channels 4q..4q+3
    float4 a1q = reinterpret_cast<const float4*>(s_a1)[q];
    float4 c1q = reinterpret_cast<const float4*>(s_c1)[q];
    const float4* gy4 = reinterpret_cast<const float4*>(g_y1);

    int stride = gridDim.x * 8;
    int m = blockIdx.x * 8 + wid;
    // initial prefetch (every warp has at least one point: 3552 <= M)
    int j = nidx[m * 32 + t];
    float qx = qp[3 * m], qy = qp[3 * m + 1], qz = qp[3 * m + 2];

    float4 fsum4 = make_float4(0.f, 0.f, 0.f, 0.f);
    float4 fsq4  = make_float4(0.f, 0.f, 0.f, 0.f);

    for (; m < M; m += stride) {
        // positions: lane = neighbor h
        float nx = sp[3 * j] - qx, ny = sp[3 * j + 1] - qy, nz = sp[3 * j + 2] - qz;
        float nn = nx * nx + ny * ny + nz * nz;

        // prefetch next point's indices / query position
        int mn = m + stride;
        int jn = 0; float qxn = 0.f, qyn = 0.f, qzn = 0.f;
        if (mn < M) {
            jn = nidx[mn * 32 + t];
            qxn = qp[3 * mn]; qyn = qp[3 * mn + 1]; qzn = qp[3 * mn + 2];
        }

        // gather: iteration i loads row h = 4*i + r, channels 4q..4q+3 (LDG.128)
        float4 v4[8];
        float4 cmax4 = make_float4(-3.4e38f, -3.4e38f, -3.4e38f, -3.4e38f);
#pragma unroll
        for (int i = 0; i < 8; i++) {
            int jh = __shfl_sync(FULL, j, 4 * i + r);
            float4 raw = gy4[jh * 8 + q];
            float4 vv;
            vv.x = lrelu(fmaf(raw.x, a1q.x, c1q.x));
            vv.y = lrelu(fmaf(raw.y, a1q.y, c1q.y));
            vv.z = lrelu(fmaf(raw.z, a1q.z, c1q.z));
            vv.w = lrelu(fmaf(raw.w, a1q.w, c1q.w));
            v4[i] = vv;
            cmax4.x = fmaxf(cmax4.x, vv.x); cmax4.y = fmaxf(cmax4.y, vv.y);
            cmax4.z = fmaxf(cmax4.z, vv.z); cmax4.w = fmaxf(cmax4.w, vv.w);
        }
        // butterfly max across r (bits 3,4 of lane id)
#pragma unroll
        for (int ofs = 8; ofs <= 16; ofs <<= 1) {
            cmax4.x = fmaxf(cmax4.x, __shfl_xor_sync(FULL, cmax4.x, ofs));
            cmax4.y = fmaxf(cmax4.y, __shfl_xor_sync(FULL, cmax4.y, ofs));
            cmax4.z = fmaxf(cmax4.z, __shfl_xor_sync(FULL, cmax4.z, ofs));
            cmax4.w = fmaxf(cmax4.w, __shfl_xor_sync(FULL, cmax4.w, ofs));
        }
        if (r == 0) reinterpret_cast<float4*>(&center_s[wid][0])[q] = cmax4;
        __syncwarp();

        // hidden[q] = lrelu(b1[q] + sum_c center[c]*wg1[c][q]); split channel range over r
        {
            float a = 0.f;
#pragma unroll
            for (int e = 0; e < 8; e++)
                a = fmaf(center_s[wid][r * 8 + e], wg1_s[r * 8 + e][q], a);
            a += __shfl_xor_sync(FULL, a, 8);
            a += __shfl_xor_sync(FULL, a, 16);
            if (t < 8) hid_s[wid][t] = lrelu(a + bg1_s[t]);
        }
        __syncwarp();
        // w = hidden @ w_g2 + b_g2, lanes 0..29  (w[k,g] = w[2k+g])
        if (t < 30) {
            float a = bg2_s[t];
#pragma unroll
            for (int k8 = 0; k8 < 8; k8++) a = fmaf(hid_s[wid][k8], wg2_s[k8][t], a);
            wv_s[wid][t] = a;
        }
        __syncwarp();
        // omega[h,g] = sum_k w[k,g] * infl[h,k]; lane = neighbor h; infl fused
        float om0 = 0.f, om1 = 0.f;
#pragma unroll
        for (int k = 0; k < 15; k++) {
            float4 kk = kp_s[k];
            float d2 = nn + kk.w - 2.f * (nx * kk.x + ny * kk.y + nz * kk.z);
            float infl = fmaxf(1.f - sqrtf(fmaxf(d2, 0.f)), 0.f);
            om0 = fmaf(wv_s[wid][2 * k], infl, om0);
            om1 = fmaf(wv_s[wid][2 * k + 1], infl, om1);
        }
        omg_s[wid][t][0] = om0;
        omg_s[wid][t][1] = om1;
        __syncwarp();
        // out[4q+e] = sum_h omega[h, g] * v[h][4q+e]; g = q>>2; rows h = 4i+r
        int g = q >> 2;
        float4 o4 = make_float4(0.f, 0.f, 0.f, 0.f);
#pragma unroll
        for (int i = 0; i < 8; i++) {
            float w = omg_s[wid][4 * i + r][g];
            o4.x = fmaf(w, v4[i].x, o4.x);
            o4.y = fmaf(w, v4[i].y, o4.y);
            o4.z = fmaf(w, v4[i].z, o4.z);
            o4.w = fmaf(w, v4[i].w, o4.w);
        }
#pragma unroll
        for (int ofs = 8; ofs <= 16; ofs <<= 1) {
            o4.x += __shfl_xor_sync(FULL, o4.x, ofs);
            o4.y += __shfl_xor_sync(FULL, o4.y, ofs);
            o4.z += __shfl_xor_sync(FULL, o4.z, ofs);
            o4.w += __shfl_xor_sync(FULL, o4.w, ofs);
        }
        if (r == 0) {
            reinterpret_cast<float4*>(g_y2 + m * 32)[q] = o4;
            fsum4.x += o4.x; fsum4.y += o4.y; fsum4.z += o4.z; fsum4.w += o4.w;
            fsq4.x = fmaf(o4.x, o4.x, fsq4.x); fsq4.y = fmaf(o4.y, o4.y, fsq4.y);
            fsq4.z = fmaf(o4.z, o4.z, fsq4.z); fsq4.w = fmaf(o4.w, o4.w, fsq4.w);
        }
        j = jn; qx = qxn; qy = qyn; qz = qzn;
    }
    // block-reduce column stats (channels 4q+e live in lanes r==0)
    __syncthreads();
    if (r == 0) reinterpret_cast<float4*>(&red_s[wid][0])[q] = fsum4;
    __syncthreads();
    if (wid == 0) {
        float s = 0.f;
#pragma unroll
        for (int i = 0; i < 8; i++) s += red_s[i][t];
        atomicAdd(&g_acc[64 + t], (double)s);
    }
    __syncthreads();
    if (r == 0) reinterpret_cast<float4*>(&red_s[wid][0])[q] = fsq4;
    __syncthreads();
    if (wid == 0) {
        float s = 0.f;
#pragma unroll
        for (int i = 0; i < 8; i++) s += red_s[i][t];
        atomicAdd(&g_acc[96 + t], (double)s);
    }
}

// ---------------- K5: z = lrelu(bn(y2)) @ w_u2  (M,32)x(32,128), + column stats ----------------
// computes conv BN affine per-block; block 0 resets stage-0 acc slots
__global__ void __launch_bounds__(256) kpi_u2_kernel(const float* __restrict__ w,
                                                     const float* __restrict__ gc,
                                                     const float* __restrict__ bc,
                                                     double invM, int M) {
    __shared__ __align__(16) float w_s[4096];     // [c2][j] 32x128
    __shared__ __align__(16) float xs[8][32];
    __shared__ float red_s[2][128];
    __shared__ float s_aC[32], s_cC[32];
    int tid = threadIdx.x;
    if (tid < 32) bn_affine(g_acc + 64, g_acc + 96, gc, bc, invM, tid, s_aC, s_cC);
    if (blockIdx.x == 0 && tid >= 64 && tid < 128) g_acc[tid - 64] = 0.0;
    for (int i = tid; i < 4096; i += 256) w_s[i] = w[i];
    int j = tid & 127, rr = tid >> 7;
    float fsum = 0.f, fsq = 0.f;
    int ntile = (M + 7) >> 3;
    for (int T = blockIdx.x; T < ntile; T += gridDim.x) {
        int base = T << 3;
        __syncthreads();
        {
            int r = tid >> 5, cc = tid & 31;
            int m = base + r;
            float v = 0.f;
            if (m < M) {
                v = g_y2[m * 32 + cc];
                v = lrelu(fmaf(v, s_aC[cc], s_cC[cc]));
            }
            xs[r][cc] = v;
        }
        __syncthreads();
        float a0 = 0.f, a1 = 0.f, a2 = 0.f, a3 = 0.f;
#pragma unroll
        for (int c2 = 0; c2 < 32; c2 += 4) {
            float4 x0 = reinterpret_cast<const float4*>(&xs[rr][0])[c2 >> 2];
            float4 x1 = reinterpret_cast<const float4*>(&xs[rr + 2][0])[c2 >> 2];
            float4 x2 = reinterpret_cast<const float4*>(&xs[rr + 4][0])[c2 >> 2];
            float4 x3 = reinterpret_cast<const float4*>(&xs[rr + 6][0])[c2 >> 2];
            float w0 = w_s[c2 * 128 + j], w1 = w_s[(c2 + 1) * 128 + j];
            float w2 = w_s[(c2 + 2) * 128 + j], w3 = w_s[(c2 + 3) * 128 + j];
            a0 = fmaf(x0.x, w0, a0); a0 = fmaf(x0.y, w1, a0); a0 = fmaf(x0.z, w2, a0); a0 = fmaf(x0.w, w3, a0);
            a1 = fmaf(x1.x, w0, a1); a1 = fmaf(x1.y, w1, a1); a1 = fmaf(x1.z, w2, a1); a1 = fmaf(x1.w, w3, a1);
            a2 = fmaf(x2.x, w0, a2); a2 = fmaf(x2.y, w1, a2); a2 = fmaf(x2.z, w2, a2); a2 = fmaf(x2.w, w3, a2);
            a3 = fmaf(x3.x, w0, a3); a3 = fmaf(x3.y, w1, a3); a3 = fmaf(x3.z, w2, a3); a3 = fmaf(x3.w, w3, a3);
        }
        int m;
        m = base + rr;     if (m < M) { g_z[m * 128 + j] = a0; fsum += a0; fsq += a0 * a0; }
        m = base + rr + 2; if (m < M) { g_z[m * 128 + j] = a1; fsum += a1; fsq += a1 * a1; }
        m = base + rr + 4; if (m < M) { g_z[m * 128 + j] = a2; fsum += a2; fsq += a2 * a2; }
        m = base + rr + 6; if (m < M) { g_z[m * 128 + j] = a3; fsum += a3; fsq += a3 * a3; }
    }
    __syncthreads();
    red_s[rr][j] = fsum; __syncthreads();
    if (rr == 0) atomicAdd(&g_acc[128 + j], (double)(red_s[0][j] + red_s[1][j]));
    __syncthreads();
    red_s[rr][j] = fsq; __syncthreads();
    if (rr == 0) atomicAdd(&g_acc[256 + j], (double)(red_s[0][j] + red_s[1][j]));
}

// ---------------- K7: out = lrelu(bn(z) + s_feats) ----------------
// computes unary2 BN affine per-block; block 0 resets stage-1 acc slots
__global__ void __launch_bounds__(256) kpi_final_kernel(const float* __restrict__ sf,
                                                        float* __restrict__ out,
                                                        const float* __restrict__ gu2,
                                                        const float* __restrict__ bu2,
                                                        double invM, int n4) {
    __shared__ __align__(16) float s_a3[128];
    __shared__ __align__(16) float s_c3[128];
    int tid = threadIdx.x;
    if (tid < 128) bn_affine(g_acc + 128, g_acc + 256, gu2, bu2, invM, tid, s_a3, s_c3);
    if (blockIdx.x == 0 && tid >= 128 && tid < 192) g_acc[tid - 64] = 0.0;
    __syncthreads();
    int i = blockIdx.x * blockDim.x + tid;
    int stride = gridDim.x * blockDim.x;
    for (; i < n4; i += stride) {
        float4 z = reinterpret_cast<const float4*>(g_z)[i];
        float4 s = reinterpret_cast<const float4*>(sf)[i];
        int c = (i << 2) & 127;
        float4 r;
        r.x = lrelu(fmaf(z.x, s_a3[c + 0], s_c3[c + 0]) + s.x);
        r.y = lrelu(fmaf(z.y, s_a3[c + 1], s_c3[c + 1]) + s.y);
        r.z = lrelu(fmaf(z.z, s_a3[c + 2], s_c3[c + 2]) + s.z);
        r.w = lrelu(fmaf(z.w, s_a3[c + 3], s_c3[c + 3]) + s.w);
        reinterpret_cast<float4*>(out)[i] = r;
    }
}

// ---------------- launch ----------------
extern "C" void kernel_launch(void* const* d_in, const int* in_sizes, int n_in,
                              void* d_out, int out_size) {
    const float* q_pts   = (const float*)d_in[0];
    const float* s_pts   = (const float*)d_in[1];
    const float* s_feats = (const float*)d_in[2];
    const int*   nidx    = (const int*)d_in[3];
    const float* kp      = (const float*)d_in[4];
    const float* w_u1    = (const float*)d_in[5];
    const float* g_u1    = (const float*)d_in[6];
    const float* b_u1    = (const float*)d_in[7];
    const float* w_g1    = (const float*)d_in[8];
    const float* b_g1    = (const float*)d_in[9];
    const float* w_g2    = (const float*)d_in[10];
    const float* b_g2    = (const float*)d_in[11];
    const float* g_c     = (const float*)d_in[12];
    const float* b_c     = (const float*)d_in[13];
    const float* w_u2    = (const float*)d_in[14];
    const float* g_u2    = (const float*)d_in[15];
    const float* b_u2    = (const float*)d_in[16];
    float* out = (float*)d_out;

    int M = in_sizes[0] / 3;
    double invM = 1.0 / (double)M;

    kpi_u1_kernel<<<NBLK, 256>>>(s_feats, w_u1, M);
    kpi_conv_kernel<<<CONVBLK, 256>>>(q_pts, s_pts, nidx, kp, w_g1, b_g1, w_g2, b_g2,
                                      g_u1, b_u1, invM, M);
    kpi_u2_kernel<<<NBLK, 256>>>(w_u2, g_c, b_c, invM, M);
    kpi_final_kernel<<<1184, 256>>>(s_feats, out, g_u2, b_u2, invM, M * 32);
}

// round 14
// speedup vs baseline: 1.6524x; 1.0475x over previous
#include <cuda_runtime.h>

#define MAXPTS 50000
#define NBLK 592
#define CONVBLK 444

// ---------------- scratch (no allocation allowed) ----------------
__device__ __align__(16) float  g_y1[MAXPTS * 32];    // unary1 pre-BN
__device__ __align__(16) float  g_y2[MAXPTS * 32];    // conv output pre-BN
__device__ __align__(16) float  g_z[MAXPTS * 128];    // unary2 pre-BN
__device__ double g_acc[384];  // [0:32) sum1 [32:64) sq1 [64:96) sumC [96:128) sqC [128:256) sum3 [256:384) sq3

__device__ __forceinline__ float lrelu(float x) { return fmaxf(x, 0.1f * x); }

// packed dual-fp32 helpers (sm_103a f32x2 path)
__device__ __forceinline__ unsigned long long pk(float lo, float hi) {
    unsigned long long r;
    asm("mov.b64 %0, {%1, %2};" : "=l"(r) : "f"(lo), "f"(hi));
    return r;
}
__device__ __forceinline__ float2 upk(unsigned long long v) {
    float2 r;
    asm("mov.b64 {%0, %1}, %2;" : "=f"(r.x), "=f"(r.y) : "l"(v));
    return r;
}
#define FMA2(d, a, b, c) \
    asm("fma.rn.f32x2 %0, %1, %2, %3;" : "=l"(d) : "l"(a), "l"(b), "l"(c))

// compute BN affine from accumulated stats: a = g/sqrt(var+eps), c = b - mean*a
// all-float path (DP only for the two cheap multiplies); rsqrtf + 1 Newton step
__device__ __forceinline__ void bn_affine(const double* __restrict__ sum,
                                          const double* __restrict__ sq,
                                          const float* __restrict__ g,
                                          const float* __restrict__ b,
                                          double invM, int t,
                                          float* __restrict__ a, float* __restrict__ c) {
    float mean = (float)(sum[t] * invM);
    float ex2  = (float)(sq[t]  * invM);
    float x = fmaxf(ex2 - mean * mean, 0.f) + 1e-5f;
    float inv = rsqrtf(x);
    inv = inv * (1.5f - 0.5f * x * inv * inv);   // Newton refine to full fp32
    float av = g[t] * inv;
    a[t] = av;
    c[t] = b[t] - mean * av;
}

// ---------------- K1: y1 = s_feats @ w_u1  (M,128)x(128,32), + column stats ----------------
// block 0 also resets stage-2 acc slots (consumed by kpi_final in the previous replay)
__global__ void __launch_bounds__(256) kpi_u1_kernel(const float* __restrict__ sf,
                                                     const float* __restrict__ w, int M) {
    __shared__ __align__(16) unsigned long long w2_s[2048];  // [c2pair 0..63][c 0..31] packed
    __shared__ __align__(16) float rows_s[32][128];
    __shared__ float red_s[8][32];
    int tid = threadIdx.x;
    if (blockIdx.x == 0) {
        g_acc[128 + tid] = 0.0;
    }
    // pack weight pairs: w2_s[p*32+c] = (w[2p][c], w[2p+1][c])
    for (int i = tid; i < 2048; i += 256) {
        int p = i >> 5, c0 = i & 31;
        w2_s[i] = pk(w[(2 * p) * 32 + c0], w[(2 * p + 1) * 32 + c0]);
    }
    int c = tid & 31, rq = tid >> 5;
    float fsum = 0.f, fsq = 0.f;
    int ntile = (M + 31) >> 5;
    for (int T = blockIdx.x; T < ntile; T += gridDim.x) {
        int base = T << 5;
        __syncthreads();
        for (int i = tid; i < 1024; i += 256) {
            int r = i >> 5, c4 = i & 31;
            int m = base + r;
            float4 v = make_float4(0.f, 0.f, 0.f, 0.f);
            if (m < M) v = reinterpret_cast<const float4*>(sf)[m * 32 + c4];
            reinterpret_cast<float4*>(&rows_s[r][0])[c4] = v;
        }
        __syncthreads();
        unsigned long long A0 = 0, A1 = 0, A2 = 0, A3 = 0;
#pragma unroll
        for (int g = 0; g < 32; g++) {   // 4 input channels per step
            unsigned long long w01 = w2_s[(2 * g) * 32 + c];
            unsigned long long w23 = w2_s[(2 * g + 1) * 32 + c];
            ulonglong2 r0 = reinterpret_cast<const ulonglong2*>(&rows_s[rq][0])[g];
            ulonglong2 r1 = reinterpret_cast<const ulonglong2*>(&rows_s[rq + 8][0])[g];
            ulonglong2 r2 = reinterpret_cast<const ulonglong2*>(&rows_s[rq + 16][0])[g];
            ulonglong2 r3 = reinterpret_cast<const ulonglong2*>(&rows_s[rq + 24][0])[g];
            FMA2(A0, r0.x, w01, A0); FMA2(A0, r0.y, w23, A0);
            FMA2(A1, r1.x, w01, A1); FMA2(A1, r1.y, w23, A1);
            FMA2(A2, r2.x, w01, A2); FMA2(A2, r2.y, w23, A2);
            FMA2(A3, r3.x, w01, A3); FMA2(A3, r3.y, w23, A3);
        }
        float2 u0 = upk(A0), u1 = upk(A1), u2 = upk(A2), u3 = upk(A3);
        float a0 = u0.x + u0.y, a1 = u1.x + u1.y, a2 = u2.x + u2.y, a3 = u3.x + u3.y;
        int m;
        m = base + rq;      if (m < M) { g_y1[m * 32 + c] = a0; fsum += a0; fsq += a0 * a0; }
        m = base + rq + 8;  if (m < M) { g_y1[m * 32 + c] = a1; fsum += a1; fsq += a1 * a1; }
        m = base + rq + 16; if (m < M) { g_y1[m * 32 + c] = a2; fsum += a2; fsq += a2 * a2; }
        m = base + rq + 24; if (m < M) { g_y1[m * 32 + c] = a3; fsum += a3; fsq += a3 * a3; }
    }
    __syncthreads();
    red_s[rq][c] = fsum; __syncthreads();
    if (rq == 0) {
        float s = 0.f;
#pragma unroll
        for (int i = 0; i < 8; i++) s += red_s[i][c];
        atomicAdd(&g_acc[c], (double)s);
    }
    __syncthreads();
    red_s[rq][c] = fsq; __syncthreads();
    if (rq == 0) {
        float s = 0.f;
#pragma unroll
        for (int i = 0; i < 8; i++) s += red_s[i][c];
        atomicAdd(&g_acc[32 + c], (double)s);
    }
}

// ---------------- K3: KPInv conv (warp per point); computes unary1 BN affine per-block ----------------
__global__ void __launch_bounds__(256, 3) kpi_conv_kernel(const float* __restrict__ qp,
                                                          const float* __restrict__ sp,
                                                          const int* __restrict__ nidx,
                                                          const float* __restrict__ kp,
                                                          const float* __restrict__ wg1,
                                                          const float* __restrict__ bg1,
                                                          const float* __restrict__ wg2,
                                                          const float* __restrict__ bg2,
                                                          const float* __restrict__ gu1,
                                                          const float* __restrict__ bu1,
                                                          double invM, int M) {
    __shared__ __align__(16) float omg_s[8][32][2];
    __shared__ __align__(16) float center_s[8][32];
    __shared__ float hid_s[8][8];
    __shared__ float wv_s[8][32];
    __shared__ __align__(16) float4 kp_s[15];   // x,y,z,|k|^2
    __shared__ float wg1_s[32][8];
    __shared__ float bg1_s[8];
    __shared__ float wg2_s[8][32];    // 30 used per row
    __shared__ float bg2_s[32];
    __shared__ __align__(16) float red_s[8][32];
    __shared__ __align__(16) float s_a1[32];
    __shared__ __align__(16) float s_c1[32];

    const unsigned FULL = 0xffffffffu;
    int tid = threadIdx.x, wid = tid >> 5, t = tid & 31;
    int r = t >> 3, q = t & 7;        // lane = r*8 + q
    // per-block BN affine for unary1 output (stage 0) — float path
    if (tid < 32) bn_affine(g_acc, g_acc + 32, gu1, bu1, invM, tid, s_a1, s_c1);
    // load small params
    if (tid >= 32 && tid < 47) {
        int kk = tid - 32;
        float kx = kp[3 * kk], ky = kp[3 * kk + 1], kz = kp[3 * kk + 2];
        kp_s[kk] = make_float4(kx, ky, kz, kx * kx + ky * ky + kz * kz);
    }
    for (int i = tid; i < 256; i += 256) wg1_s[i >> 3][i & 7] = wg1[i];
    if (tid >= 64 && tid < 72) bg1_s[tid - 64] = bg1[tid - 64];
    if (tid < 240) wg2_s[tid / 30][tid % 30] = wg2[tid];
    if (tid >= 96 && tid < 126) bg2_s[tid - 96] = bg2[tid - 96];
    __syncthreads();

    // per-lane BN affine for channels 4q..4q+3
    float4 a1q = reinterpret_cast<const float4*>(s_a1)[q];
    float4 c1q = reinterpret_cast<const float4*>(s_c1)[q];
    const float4* gy4 = reinterpret_cast<const float4*>(g_y1);

    int stride = gridDim.x * 8;
    int m = blockIdx.x * 8 + wid;
    // initial prefetch (every warp has at least one point: 3552 <= M)
    int j = nidx[m * 32 + t];
    float qx = qp[3 * m], qy = qp[3 * m + 1], qz = qp[3 * m + 2];

    float4 fsum4 = make_float4(0.f, 0.f, 0.f, 0.f);
    float4 fsq4  = make_float4(0.f, 0.f, 0.f, 0.f);

    for (; m < M; m += stride) {
        // positions: lane = neighbor h
        float nx = sp[3 * j] - qx, ny = sp[3 * j + 1] - qy, nz = sp[3 * j + 2] - qz;
        float nn = nx * nx + ny * ny + nz * nz;

        // prefetch next point's indices / query position
        int mn = m + stride;
        int jn = 0; float qxn = 0.f, qyn = 0.f, qzn = 0.f;
        if (mn < M) {
            jn = nidx[mn * 32 + t];
            qxn = qp[3 * mn]; qyn = qp[3 * mn + 1]; qzn = qp[3 * mn + 2];
        }

        // gather: iteration i loads row h = 4*i + r, channels 4q..4q+3 (LDG.128)
        float4 v4[8];
        float4 cmax4 = make_float4(-3.4e38f, -3.4e38f, -3.4e38f, -3.4e38f);
#pragma unroll
        for (int i = 0; i < 8; i++) {
            int jh = __shfl_sync(FULL, j, 4 * i + r);
            float4 raw = gy4[jh * 8 + q];
            float4 vv;
            vv.x = lrelu(fmaf(raw.x, a1q.x, c1q.x));
            vv.y = lrelu(fmaf(raw.y, a1q.y, c1q.y));
            vv.z = lrelu(fmaf(raw.z, a1q.z, c1q.z));
            vv.w = lrelu(fmaf(raw.w, a1q.w, c1q.w));
            v4[i] = vv;
            cmax4.x = fmaxf(cmax4.x, vv.x); cmax4.y = fmaxf(cmax4.y, vv.y);
            cmax4.z = fmaxf(cmax4.z, vv.z); cmax4.w = fmaxf(cmax4.w, vv.w);
        }
        // butterfly max across r (bits 3,4 of lane id)
#pragma unroll
        for (int ofs = 8; ofs <= 16; ofs <<= 1) {
            cmax4.x = fmaxf(cmax4.x, __shfl_xor_sync(FULL, cmax4.x, ofs));
            cmax4.y = fmaxf(cmax4.y, __shfl_xor_sync(FULL, cmax4.y, ofs));
            cmax4.z = fmaxf(cmax4.z, __shfl_xor_sync(FULL, cmax4.z, ofs));
            cmax4.w = fmaxf(cmax4.w, __shfl_xor_sync(FULL, cmax4.w, ofs));
        }
        if (r == 0) reinterpret_cast<float4*>(&center_s[wid][0])[q] = cmax4;
        __syncwarp();

        // hidden[q] = lrelu(b1[q] + sum_c center[c]*wg1[c][q]); split channel range over r
        {
            float a = 0.f;
#pragma unroll
            for (int e = 0; e < 8; e++)
                a = fmaf(center_s[wid][r * 8 + e], wg1_s[r * 8 + e][q], a);
            a += __shfl_xor_sync(FULL, a, 8);
            a += __shfl_xor_sync(FULL, a, 16);
            if (t < 8) hid_s[wid][t] = lrelu(a + bg1_s[t]);
        }
        __syncwarp();
        // w = hidden @ w_g2 + b_g2, lanes 0..29  (w[k,g] = w[2k+g])
        if (t < 30) {
            float a = bg2_s[t];
#pragma unroll
            for (int k8 = 0; k8 < 8; k8++) a = fmaf(hid_s[wid][k8], wg2_s[k8][t], a);
            wv_s[wid][t] = a;
        }
        __syncwarp();
        // omega[h,g] = sum_k w[k,g] * infl[h,k]; lane = neighbor h; infl fused
        float om0 = 0.f, om1 = 0.f;
#pragma unroll
        for (int k = 0; k < 15; k++) {
            float4 kk = kp_s[k];
            float d2 = nn + kk.w - 2.f * (nx * kk.x + ny * kk.y + nz * kk.z);
            float infl = fmaxf(1.f - sqrtf(fmaxf(d2, 0.f)), 0.f);
            om0 = fmaf(wv_s[wid][2 * k], infl, om0);
            om1 = fmaf(wv_s[wid][2 * k + 1], infl, om1);
        }
        omg_s[wid][t][0] = om0;
        omg_s[wid][t][1] = om1;
        __syncwarp();
        // out[4q+e] = sum_h omega[h, g] * v[h][4q+e]; g = q>>2; rows h = 4i+r
        int g = q >> 2;
        float4 o4 = make_float4(0.f, 0.f, 0.f, 0.f);
#pragma unroll
        for (int i = 0; i < 8; i++) {
            float w = omg_s[wid][4 * i + r][g];
            o4.x = fmaf(w, v4[i].x, o4.x);
            o4.y = fmaf(w, v4[i].y, o4.y);
            o4.z = fmaf(w, v4[i].z, o4.z);
            o4.w = fmaf(w, v4[i].w, o4.w);
        }
#pragma unroll
        for (int ofs = 8; ofs <= 16; ofs <<= 1) {
            o4.x += __shfl_xor_sync(FULL, o4.x, ofs);
            o4.y += __shfl_xor_sync(FULL, o4.y, ofs);
            o4.z += __shfl_xor_sync(FULL, o4.z, ofs);
            o4.w += __shfl_xor_sync(FULL, o4.w, ofs);
        }
        if (r == 0) {
            reinterpret_cast<float4*>(g_y2 + m * 32)[q] = o4;
            fsum4.x += o4.x; fsum4.y += o4.y; fsum4.z += o4.z; fsum4.w += o4.w;
            fsq4.x = fmaf(o4.x, o4.x, fsq4.x); fsq4.y = fmaf(o4.y, o4.y, fsq4.y);
            fsq4.z = fmaf(o4.z, o4.z, fsq4.z); fsq4.w = fmaf(o4.w, o4.w, fsq4.w);
        }
        j = jn; qx = qxn; qy = qyn; qz = qzn;
    }
    // block-reduce column stats (channels 4q+e live in lanes r==0)
    __syncthreads();
    if (r == 0) reinterpret_cast<float4*>(&red_s[wid][0])[q] = fsum4;
    __syncthreads();
    if (wid == 0) {
        float s = 0.f;
#pragma unroll
        for (int i = 0; i < 8; i++) s += red_s[i][t];
        atomicAdd(&g_acc[64 + t], (double)s);
    }
    __syncthreads();
    if (r == 0) reinterpret_cast<float4*>(&red_s[wid][0])[q] = fsq4;
    __syncthreads();
    if (wid == 0) {
        float s = 0.f;
#pragma unroll
        for (int i = 0; i < 8; i++) s += red_s[i][t];
        atomicAdd(&g_acc[96 + t], (double)s);
    }
}

// ---------------- K5: z = lrelu(bn(y2)) @ w_u2  (M,32)x(32,128), + column stats ----------------
// computes conv BN affine per-block; block 0 resets stage-0 acc slots
__global__ void __launch_bounds__(256) kpi_u2_kernel(const float* __restrict__ w,
                                                     const float* __restrict__ gc,
                                                     const float* __restrict__ bc,
                                                     double invM, int M) {
    __shared__ __align__(16) unsigned long long w2_s[2048];  // [c2pair 0..15][j 0..127] packed
    __shared__ __align__(16) float xs[8][32];
    __shared__ float red_s[2][128];
    __shared__ float s_aC[32], s_cC[32];
    int tid = threadIdx.x;
    if (tid < 32) bn_affine(g_acc + 64, g_acc + 96, gc, bc, invM, tid, s_aC, s_cC);
    if (blockIdx.x == 0 && tid >= 64 && tid < 128) g_acc[tid - 64] = 0.0;
    // pack weight pairs: w2_s[p*128+j] = (w[2p][j], w[2p+1][j])
    for (int i = tid; i < 2048; i += 256) {
        int p = i >> 7, jj = i & 127;
        w2_s[i] = pk(w[(2 * p) * 128 + jj], w[(2 * p + 1) * 128 + jj]);
    }
    int j = tid & 127, rr = tid >> 7;
    float fsum = 0.f, fsq = 0.f;
    int ntile = (M + 7) >> 3;
    for (int T = blockIdx.x; T < ntile; T += gridDim.x) {
        int base = T << 3;
        __syncthreads();
        {
            int r = tid >> 5, cc = tid & 31;
            int m = base + r;
            float v = 0.f;
            if (m < M) {
                v = g_y2[m * 32 + cc];
                v = lrelu(fmaf(v, s_aC[cc], s_cC[cc]));
            }
            xs[r][cc] = v;
        }
        __syncthreads();
        unsigned long long A0 = 0, A1 = 0, A2 = 0, A3 = 0;
#pragma unroll
        for (int g = 0; g < 8; g++) {   // 4 input channels per step
            unsigned long long w01 = w2_s[(2 * g) * 128 + j];
            unsigned long long w23 = w2_s[(2 * g + 1) * 128 + j];
            ulonglong2 x0 = reinterpret_cast<const ulonglong2*>(&xs[rr][0])[g];
            ulonglong2 x1 = reinterpret_cast<const ulonglong2*>(&xs[rr + 2][0])[g];
            ulonglong2 x2 = reinterpret_cast<const ulonglong2*>(&xs[rr + 4][0])[g];
            ulonglong2 x3 = reinterpret_cast<const ulonglong2*>(&xs[rr + 6][0])[g];
            FMA2(A0, x0.x, w01, A0); FMA2(A0, x0.y, w23, A0);
            FMA2(A1, x1.x, w01, A1); FMA2(A1, x1.y, w23, A1);
            FMA2(A2, x2.x, w01, A2); FMA2(A2, x2.y, w23, A2);
            FMA2(A3, x3.x, w01, A3); FMA2(A3, x3.y, w23, A3);
        }
        float2 u0 = upk(A0), u1 = upk(A1), u2 = upk(A2), u3 = upk(A3);
        float a0 = u0.x + u0.y, a1 = u1.x + u1.y, a2 = u2.x + u2.y, a3 = u3.x + u3.y;
        int m;
        m = base + rr;     if (m < M) { g_z[m * 128 + j] = a0; fsum += a0; fsq += a0 * a0; }
        m = base + rr + 2; if (m < M) { g_z[m * 128 + j] = a1; fsum += a1; fsq += a1 * a1; }
        m = base + rr + 4; if (m < M) { g_z[m * 128 + j] = a2; fsum += a2; fsq += a2 * a2; }
        m = base + rr + 6; if (m < M) { g_z[m * 128 + j] = a3; fsum += a3; fsq += a3 * a3; }
    }
    __syncthreads();
    red_s[rr][j] = fsum; __syncthreads();
    if (rr == 0) atomicAdd(&g_acc[128 + j], (double)(red_s[0][j] + red_s[1][j]));
    __syncthreads();
    red_s[rr][j] = fsq; __syncthreads();
    if (rr == 0) atomicAdd(&g_acc[256 + j], (double)(red_s[0][j] + red_s[1][j]));
}

// ---------------- K7: out = lrelu(bn(z) + s_feats) ----------------
// computes unary2 BN affine per-block; block 0 resets stage-1 acc slots
__global__ void __launch_bounds__(256) kpi_final_kernel(const float* __restrict__ sf,
                                                        float* __restrict__ out,
                                                        const float* __restrict__ gu2,
                                                        const float* __restrict__ bu2,
                                                        double invM, int n4) {
    __shared__ __align__(16) float s_a3[128];
    __shared__ __align__(16) float s_c3[128];
    int tid = threadIdx.x;
    if (tid < 128) bn_affine(g_acc + 128, g_acc + 256, gu2, bu2, invM, tid, s_a3, s_c3);
    if (blockIdx.x == 0 && tid >= 128 && tid < 192) g_acc[tid - 64] = 0.0;
    __syncthreads();
    int i = blockIdx.x * blockDim.x + tid;
    int stride = gridDim.x * blockDim.x;
    for (; i < n4; i += stride) {
        float4 z = reinterpret_cast<const float4*>(g_z)[i];
        float4 s = reinterpret_cast<const float4*>(sf)[i];
        int c = (i << 2) & 127;
        float4 r;
        r.x = lrelu(fmaf(z.x, s_a3[c + 0], s_c3[c + 0]) + s.x);
        r.y = lrelu(fmaf(z.y, s_a3[c + 1], s_c3[c + 1]) + s.y);
        r.z = lrelu(fmaf(z.z, s_a3[c + 2], s_c3[c + 2]) + s.z);
        r.w = lrelu(fmaf(z.w, s_a3[c + 3], s_c3[c + 3]) + s.w);
        reinterpret_cast<float4*>(out)[i] = r;
    }
}

// ---------------- launch ----------------
extern "C" void kernel_launch(void* const* d_in, const int* in_sizes, int n_in,
                              void* d_out, int out_size) {
    const float* q_pts   = (const float*)d_in[0];
    const float* s_pts   = (const float*)d_in[1];
    const float* s_feats = (const float*)d_in[2];
    const int*   nidx    = (const int*)d_in[3];
    const float* kp      = (const float*)d_in[4];
    const float* w_u1    = (const float*)d_in[5];
    const float* g_u1    = (const float*)d_in[6];
    const float* b_u1    = (const float*)d_in[7];
    const float* w_g1    = (const float*)d_in[8];
    const float* b_g1    = (const float*)d_in[9];
    const float* w_g2    = (const float*)d_in[10];
    const float* b_g2    = (const float*)d_in[11];
    const float* g_c     = (const float*)d_in[12];
    const float* b_c     = (const float*)d_in[13];
    const float* w_u2    = (const float*)d_in[14];
    const float* g_u2    = (const float*)d_in[15];
    const float* b_u2    = (const float*)d_in[16];
    float* out = (float*)d_out;

    int M = in_sizes[0] / 3;
    double invM = 1.0 / (double)M;

    kpi_u1_kernel<<<NBLK, 256>>>(s_feats, w_u1, M);
    kpi_conv_kernel<<<CONVBLK, 256>>>(q_pts, s_pts, nidx, kp, w_g1, b_g1, w_g2, b_g2,
                                      g_u1, b_u1, invM, M);
    kpi_u2_kernel<<<NBLK, 256>>>(w_u2, g_c, b_c, invM, M);
    kpi_final_kernel<<<1184, 256>>>(s_feats, out, g_u2, b_u2, invM, M * 32);
}